// round 11
// baseline (speedup 1.0000x reference)
#include <cuda_runtime.h>
#include <cuda_bf16.h>
#include <math.h>
#include <stdint.h>

#define BSZ  2
#define CCH  256
#define NTOK 4096
#define NGRP 16
#define CPG  (CCH/NGRP)   // 16

// ---------------- scratch (device globals) ----------------------------------
__device__ __nv_bfloat16 g_wpack[1024*CCH];          // rows 0-767: wq|wk|wv, 768-1023: wp
__device__ float         g_bqkv[768];
__device__ __nv_bfloat16 g_hnT[BSZ*NTOK*CCH];        // [b*n][c]
__device__ __nv_bfloat16 g_qkv[BSZ*NTOK*768];        // [b*n][q|k|v], q pre-scaled 1/16
__device__ float         g_oap[2][BSZ*NTOK*CCH];     // partial O per kv-split
__device__ float         g_rsp[2][BSZ*NTOK];         // partial rowsums
__device__ float         g_stats[BSZ*NGRP*2];

// ---------------- PTX helpers (sm_80-level only) -----------------------------
__device__ __forceinline__ uint32_t smem_u32(const void* p) {
    uint32_t a;
    asm("{ .reg .u64 t; cvta.to.shared.u64 t, %1; cvt.u32.u64 %0, t; }" : "=r"(a) : "l"(p));
    return a;
}
__device__ __forceinline__ void cp16(uint32_t s, const void* g) {
    asm volatile("cp.async.cg.shared.global [%0], [%1], 16;" :: "r"(s), "l"(g));
}
__device__ __forceinline__ void cp_commit() {
    asm volatile("cp.async.commit_group;" ::: "memory");
}
template<int N>
__device__ __forceinline__ void cp_wait() {
    asm volatile("cp.async.wait_group %0;" :: "n"(N) : "memory");
}
__device__ __forceinline__ void ldm4(uint32_t* r, uint32_t a) {
    asm volatile("ldmatrix.sync.aligned.m8n8.x4.shared.b16 {%0,%1,%2,%3}, [%4];"
                 : "=r"(r[0]), "=r"(r[1]), "=r"(r[2]), "=r"(r[3]) : "r"(a));
}
__device__ __forceinline__ void ldm4t(uint32_t* r, uint32_t a) {
    asm volatile("ldmatrix.sync.aligned.m8n8.x4.trans.shared.b16 {%0,%1,%2,%3}, [%4];"
                 : "=r"(r[0]), "=r"(r[1]), "=r"(r[2]), "=r"(r[3]) : "r"(a));
}
__device__ __forceinline__ void sts32(uint32_t a, uint32_t v) {
    asm volatile("st.shared.b32 [%0], %1;" :: "r"(a), "r"(v) : "memory");
}
__device__ __forceinline__ void sts128(uint32_t a, uint4 v) {
    asm volatile("st.shared.v4.b32 [%0], {%1,%2,%3,%4};"
                 :: "r"(a), "r"(v.x), "r"(v.y), "r"(v.z), "r"(v.w) : "memory");
}
__device__ __forceinline__ void mma_bf16(float* c, const uint32_t* a, const uint32_t* b) {
    asm volatile(
        "mma.sync.aligned.m16n8k16.row.col.f32.bf16.bf16.f32 "
        "{%0,%1,%2,%3}, {%4,%5,%6,%7}, {%8,%9}, {%0,%1,%2,%3};"
        : "+f"(c[0]), "+f"(c[1]), "+f"(c[2]), "+f"(c[3])
        : "r"(a[0]), "r"(a[1]), "r"(a[2]), "r"(a[3]), "r"(b[0]), "r"(b[1]));
}

// ---------------- small-tile HMMA GEMM: 64x128 tiles, 128 threads ------------
// C[M][N] = A[M][K] * B[N][K]^T.
// MODE 1 (QKV): A=g_hnT, B=g_wpack; bf16 C to g_qkv (+col bias, q cols scaled 1/16).
// MODE 2 (proj): A=wp, B built on the fly from g_oap/g_rsp (combine fused);
//                fp32 residual epilogue out[b][c][n] = x + acc + bias[c].
template<int MODE>
__global__ void __launch_bounds__(128, 3)
gemm_mma(const __nv_bfloat16* __restrict__ A, const __nv_bfloat16* __restrict__ Bm,
         void* __restrict__ Cm, const float* __restrict__ bias,
         const float* __restrict__ xres) {
    extern __shared__ char smem[];
    const uint32_t sbase = smem_u32(smem);
    const int tid = threadIdx.x;
    const int wid = tid >> 5, lane = tid & 31;
    const int bm = blockIdx.y * 64, bn = blockIdx.x * 128;
    const int K = 256;

    const __nv_bfloat16* Ab = A + (long)bm * K;
    const __nv_bfloat16* Bb = (MODE == 1) ? Bm + (long)bn * K : nullptr;

    const int wm = (wid >> 1) * 32;      // 0 / 32
    const int wn = (wid & 1) * 64;       // 0 / 64

    float acc[2][8][4] = {};

    // stage: A 64x128B @0, B 128x128B @8192; stride 24576, 3 stages.
    auto issueA = [&](int st, int k0) {
        uint32_t sa = sbase + st * 24576;
        #pragma unroll
        for (int j = 0; j < 4; j++) {
            int idx = tid + j * 128;
            int row = idx >> 3, ch = idx & 7;
            cp16(sa + row * 128 + ((ch ^ (row & 7)) << 4),
                 Ab + (long)row * K + k0 + ch * 8);
        }
    };
    auto issueB1 = [&](int st, int k0) {
        uint32_t sb = sbase + st * 24576 + 8192;
        #pragma unroll
        for (int j = 0; j < 8; j++) {
            int idx = tid + j * 128;
            int row = idx >> 3, ch = idx & 7;
            cp16(sb + row * 128 + ((ch ^ (row & 7)) << 4),
                 Bb + (long)row * K + k0 + ch * 8);
        }
    };
    // MODE 2: synchronous fused combine: B[row=token, ch] = (oap0+oap1)*inv -> bf16
    auto loadB2 = [&](int st, int k0) {
        uint32_t sb = sbase + st * 24576 + 8192;
        #pragma unroll
        for (int j = 0; j < 8; j++) {
            int idx = tid + j * 128;
            int row = idx >> 3, ch = idx & 7;          // 8 channels per chunk
            long t = bn + row;
            float inv = 1.0f / (g_rsp[0][t] + g_rsp[1][t]);
            const float4* a0 = (const float4*)&g_oap[0][t * 256 + k0 + ch * 8];
            const float4* a1 = (const float4*)&g_oap[1][t * 256 + k0 + ch * 8];
            float4 u0 = a0[0], u1 = a0[1];
            float4 w0 = a1[0], w1 = a1[1];
            __nv_bfloat162 h0 = __floats2bfloat162_rn((u0.x + w0.x) * inv, (u0.y + w0.y) * inv);
            __nv_bfloat162 h1 = __floats2bfloat162_rn((u0.z + w0.z) * inv, (u0.w + w0.w) * inv);
            __nv_bfloat162 h2 = __floats2bfloat162_rn((u1.x + w1.x) * inv, (u1.y + w1.y) * inv);
            __nv_bfloat162 h3 = __floats2bfloat162_rn((u1.z + w1.z) * inv, (u1.w + w1.w) * inv);
            uint4 pk;
            pk.x = *(uint32_t*)&h0; pk.y = *(uint32_t*)&h1;
            pk.z = *(uint32_t*)&h2; pk.w = *(uint32_t*)&h3;
            sts128(sb + row * 128 + ((ch ^ (row & 7)) << 4), pk);
        }
    };

    if (MODE == 1) { issueA(0, 0); issueB1(0, 0); cp_commit();
                     issueA(1, 64); issueB1(1, 64); cp_commit(); }
    else           { issueA(0, 0); cp_commit(); issueA(1, 64); cp_commit(); }

    for (int it = 0; it < 4; it++) {
        cp_wait<1>();
        if (MODE == 2) loadB2(it % 3, it * 64);
        __syncthreads();
        const int st = it % 3;
        uint32_t a_base = sbase + st * 24576;
        uint32_t b_base = a_base + 8192;

        const int rowa = wm + (lane & 15);
        const int swa = rowa & 7;
        const int rowb = wn + ((lane >> 4) & 1) * 8 + (lane & 7);

        #pragma unroll
        for (int ks = 0; ks < 4; ks++) {
            uint32_t af[2][4];
            const int chA = ks * 2 + (lane >> 4);
            #pragma unroll
            for (int mi = 0; mi < 2; mi++)
                ldm4(af[mi], a_base + (rowa + mi * 16) * 128 + ((chA ^ swa) << 4));

            uint32_t bf[8][2];
            const int chB = ks * 2 + ((lane >> 3) & 1);
            #pragma unroll
            for (int np = 0; np < 4; np++) {
                int rb = rowb + np * 16;
                uint32_t r[4];
                ldm4(r, b_base + rb * 128 + ((chB ^ (rb & 7)) << 4));
                bf[np * 2][0] = r[0]; bf[np * 2][1] = r[1];
                bf[np * 2 + 1][0] = r[2]; bf[np * 2 + 1][1] = r[3];
            }
            #pragma unroll
            for (int mi = 0; mi < 2; mi++)
                #pragma unroll
                for (int ni = 0; ni < 8; ni++)
                    mma_bf16(acc[mi][ni], af[mi], bf[ni]);
        }
        __syncthreads();
        if (it + 2 < 4) {
            int ns = (it + 2) % 3;                       // FIXED: wrap stage index
            if (MODE == 1) { issueA(ns, (it + 2) * 64); issueB1(ns, (it + 2) * 64); }
            else           issueA(ns, (it + 2) * 64);
        }
        cp_commit();
    }

    const int r0 = bm + wm + (lane >> 2);
    const int c0 = bn + wn + (lane & 3) * 2;
    #pragma unroll
    for (int mi = 0; mi < 2; mi++) {
        #pragma unroll
        for (int ni = 0; ni < 8; ni++) {
            int rr = r0 + mi * 16;
            int cc = c0 + ni * 8;
            float v0 = acc[mi][ni][0];
            float v1 = acc[mi][ni][1];
            float v2 = acc[mi][ni][2];
            float v3 = acc[mi][ni][3];
            if (MODE == 1) {
                float b0 = bias[cc], b1 = bias[cc + 1];
                v0 += b0; v1 += b1; v2 += b0; v3 += b1;
                if (cc < 256) { v0 *= 0.0625f; v1 *= 0.0625f; v2 *= 0.0625f; v3 *= 0.0625f; }
                __nv_bfloat16* Cp = (__nv_bfloat16*)Cm;
                *(__nv_bfloat162*)(Cp + (long)rr * 768 + cc) = __floats2bfloat162_rn(v0, v1);
                *(__nv_bfloat162*)(Cp + (long)(rr + 8) * 768 + cc) = __floats2bfloat162_rn(v2, v3);
            } else {
                float ba = bias[rr], bb = bias[rr + 8];
                int b = cc >> 12, n = cc & 4095;
                long i0 = ((long)b * CCH + rr) * NTOK + n;
                long i1 = ((long)b * CCH + rr + 8) * NTOK + n;
                float2 x0 = *(const float2*)(xres + i0);
                float2 x1 = *(const float2*)(xres + i1);
                float* Cp = (float*)Cm;
                float2 o0; o0.x = v0 + ba + x0.x; o0.y = v1 + ba + x0.y;
                float2 o1; o1.x = v2 + bb + x1.x; o1.y = v3 + bb + x1.y;
                *(float2*)(Cp + i0) = o0;
                *(float2*)(Cp + i1) = o1;
            }
        }
    }
}

// ---------------- flash v5: Br=128, 8 warps, kv-split=2 (unchanged) ----------
__device__ __forceinline__ uint32_t fswz(int row, int byteoff) {     // 512B rows
    return (uint32_t)(row * 512 + (byteoff & ~0x70) +
                      (((((byteoff >> 4) & 7) ^ (row & 7))) << 4));
}
__device__ __forceinline__ uint32_t pswz(int row, int byteoff) {     // 128B rows
    return (uint32_t)(row * 128 + (byteoff & 15) +
                      (((((byteoff >> 4) & 7) ^ (row & 7))) << 4));
}

__global__ void __launch_bounds__(256, 1)
flash_k(const __nv_bfloat16* __restrict__ qkv,
        float* __restrict__ oap, float* __restrict__ rsp) {
    extern __shared__ char smem[];
    const uint32_t sQ = smem_u32(smem);
    const uint32_t sP = sQ + 65536;
    const uint32_t sKV = sQ + 81920;
    const int tid = threadIdx.x, wid = tid >> 5, lane = tid & 31;
    const int m = wid >> 1, kvh = wid & 1;
    const int qt = blockIdx.x, b = blockIdx.y, sp = blockIdx.z;

    const __nv_bfloat16* qg = qkv + ((long)b * NTOK + qt * 128) * 768;
    const __nv_bfloat16* kg = qkv + ((long)b * NTOK + sp * (NTOK / 2)) * 768 + 256;
    const __nv_bfloat16* vg = kg + 256;

    #pragma unroll
    for (int j = 0; j < 16; j++) {
        int idx = tid + j * 256;
        int row = idx >> 5, ch = idx & 31;
        cp16(sQ + fswz(row, ch * 16), qg + (long)row * 768 + ch * 8);
    }
    auto loadKV = [&](int it, int stage) {
        const __nv_bfloat16* kt = kg + (long)it * 64 * 768;
        const __nv_bfloat16* vt = vg + (long)it * 64 * 768;
        uint32_t sK = sKV + stage * 65536;
        uint32_t sV = sK + 32768;
        #pragma unroll
        for (int j = 0; j < 8; j++) {
            int idx = tid + j * 256;
            int row = idx >> 5, ch = idx & 31;
            cp16(sK + fswz(row, ch * 16), kt + (long)row * 768 + ch * 8);
            cp16(sV + fswz(row, ch * 16), vt + (long)row * 768 + ch * 8);
        }
        cp_commit();
    };
    loadKV(0, 0);

    float oacc[2][16][4] = {};
    float rs[4] = {0.f, 0.f, 0.f, 0.f};
    const int NIT = NTOK / 2 / 64;   // 32

    for (int it = 0; it < NIT; it++) {
        cp_wait<0>();
        __syncthreads();
        if (it + 1 < NIT) loadKV(it + 1, (it + 1) & 1);

        uint32_t sK = sKV + (it & 1) * 65536;
        uint32_t sV = sK + 32768;

        {
            float sacc[2][4][4] = {};
            const int qrow = m * 32 + (lane & 15);
            const int qh = ((lane >> 4) & 1) * 16;
            const int krow = kvh * 32 + ((lane >> 4) & 1) * 8 + (lane & 7);
            const int kh = ((lane >> 3) & 1) * 16;
            #pragma unroll
            for (int kk = 0; kk < 16; kk++) {
                uint32_t aq[2][4];
                ldm4(aq[0], sQ + fswz(qrow,      kk * 32 + qh));
                ldm4(aq[1], sQ + fswz(qrow + 16, kk * 32 + qh));
                #pragma unroll
                for (int nb = 0; nb < 2; nb++) {
                    uint32_t r[4];
                    ldm4(r, sK + fswz(krow + nb * 16, kk * 32 + kh));
                    uint32_t b0[2] = {r[0], r[1]}, b1[2] = {r[2], r[3]};
                    #pragma unroll
                    for (int mi = 0; mi < 2; mi++) {
                        mma_bf16(sacc[mi][nb * 2],     aq[mi], b0);
                        mma_bf16(sacc[mi][nb * 2 + 1], aq[mi], b1);
                    }
                }
            }
            #pragma unroll
            for (int mi = 0; mi < 2; mi++)
                #pragma unroll
                for (int nj = 0; nj < 4; nj++) {
                    float e0 = __expf(sacc[mi][nj][0]);
                    float e1 = __expf(sacc[mi][nj][1]);
                    float e2 = __expf(sacc[mi][nj][2]);
                    float e3 = __expf(sacc[mi][nj][3]);
                    rs[mi * 2]     += e0 + e1;
                    rs[mi * 2 + 1] += e2 + e3;
                    __nv_bfloat162 p0 = __floats2bfloat162_rn(e0, e1);
                    __nv_bfloat162 p1 = __floats2bfloat162_rn(e2, e3);
                    int prow = m * 32 + mi * 16 + (lane >> 2);
                    int pcol = (kvh * 32 + nj * 8 + (lane & 3) * 2) * 2;
                    sts32(sP + pswz(prow,     pcol), *(uint32_t*)&p0);
                    sts32(sP + pswz(prow + 8, pcol), *(uint32_t*)&p1);
                }
        }
        __syncthreads();

        const int vrow0 = (lane & 7) + ((lane >> 3) & 1) * 8;
        const int vh = ((lane >> 4) & 1) * 16;
        #pragma unroll
        for (int T = 0; T < 4; T++) {
            uint32_t pa[2][4];
            #pragma unroll
            for (int mi = 0; mi < 2; mi++) {
                int arow = m * 32 + mi * 16 + (lane & 15);
                int abyte = T * 32 + ((lane >> 4) & 1) * 16;
                ldm4(pa[mi], sP + pswz(arow, abyte));
            }
            const int vr = T * 16 + vrow0;
            #pragma unroll
            for (int cb = 0; cb < 8; cb++) {
                uint32_t vb[4];
                ldm4t(vb, sV + fswz(vr, kvh * 256 + cb * 32 + vh));
                #pragma unroll
                for (int mi = 0; mi < 2; mi++) {
                    mma_bf16(oacc[mi][cb * 2],     pa[mi], vb);
                    mma_bf16(oacc[mi][cb * 2 + 1], pa[mi], vb + 2);
                }
            }
        }
    }
    __syncthreads();

    #pragma unroll
    for (int j = 0; j < 4; j++) {
        rs[j] += __shfl_xor_sync(0xFFFFFFFFu, rs[j], 1);
        rs[j] += __shfl_xor_sync(0xFFFFFFFFu, rs[j], 2);
    }
    float* rsb = (float*)(smem + 81920);
    if (kvh == 1 && (lane & 3) == 0) {
        #pragma unroll
        for (int mi = 0; mi < 2; mi++)
            #pragma unroll
            for (int h = 0; h < 2; h++)
                rsb[m * 32 + mi * 16 + h * 8 + (lane >> 2)] = rs[mi * 2 + h];
    }
    __syncthreads();
    long tokbase = (long)b * NTOK + qt * 128 + m * 32;
    if (kvh == 0 && (lane & 3) == 0) {
        #pragma unroll
        for (int mi = 0; mi < 2; mi++)
            #pragma unroll
            for (int h = 0; h < 2; h++) {
                int r = mi * 16 + h * 8 + (lane >> 2);
                rsp[(long)sp * BSZ * NTOK + tokbase + r] = rs[mi * 2 + h] + rsb[m * 32 + r];
            }
    }
    float* ob = oap + (long)sp * BSZ * NTOK * CCH;
    int r = lane >> 2, cq = (lane & 3) * 2;
    #pragma unroll
    for (int mi = 0; mi < 2; mi++) {
        long row0 = tokbase + mi * 16 + r;
        #pragma unroll
        for (int j = 0; j < 16; j++) {
            int col = kvh * 128 + j * 8 + cq;
            float2 p0; p0.x = oacc[mi][j][0]; p0.y = oacc[mi][j][1];
            float2 p1; p1.x = oacc[mi][j][2]; p1.y = oacc[mi][j][3];
            *(float2*)(ob + row0 * CCH + col) = p0;
            *(float2*)(ob + (row0 + 8) * CCH + col) = p1;
        }
    }
}

// ---------------- GroupNorm stats (float4, 1024 threads) ---------------------
__global__ void gn_stats_k(const float* __restrict__ x) {
    int bg = blockIdx.x;
    int b = bg >> 4, g = bg & 15;
    const float4* base = (const float4*)(x + ((long)b * CCH + (long)g * CPG) * NTOK);
    float s = 0.f, s2 = 0.f;
    #pragma unroll 4
    for (int i = threadIdx.x; i < CPG * NTOK / 4; i += 1024) {
        float4 v = base[i];
        s  += v.x + v.y + v.z + v.w;
        s2 += v.x * v.x + v.y * v.y + v.z * v.z + v.w * v.w;
    }
    __shared__ float r1[1024], r2[1024];
    r1[threadIdx.x] = s; r2[threadIdx.x] = s2;
    __syncthreads();
    for (int st = 512; st > 0; st >>= 1) {
        if (threadIdx.x < st) {
            r1[threadIdx.x] += r1[threadIdx.x + st];
            r2[threadIdx.x] += r2[threadIdx.x + st];
        }
        __syncthreads();
    }
    if (threadIdx.x == 0) {
        const float invn = 1.0f / (float)(CPG * NTOK);
        float m = r1[0] * invn;
        float var = r2[0] * invn - m * m;
        g_stats[bg * 2] = m;
        g_stats[bg * 2 + 1] = rsqrtf(var + 1e-6f);
    }
}

// --------- fused GroupNorm-apply + transpose -> bf16 [b*n][c] ----------------
__global__ void gn_apply_t_k(const float* __restrict__ x,
                             const float* __restrict__ gamma,
                             const float* __restrict__ beta) {
    __shared__ __nv_bfloat16 t[32][33];
    int n0 = blockIdx.x * 32, c0 = blockIdx.y * 32, b = blockIdx.z;
    int c = c0 + threadIdx.y;
    int g = c >> 4;
    float m = g_stats[(b * NGRP + g) * 2];
    float r = g_stats[(b * NGRP + g) * 2 + 1];
    float v = x[((long)b * CCH + c) * NTOK + n0 + threadIdx.x];
    t[threadIdx.y][threadIdx.x] = __float2bfloat16((v - m) * r * gamma[c] + beta[c]);
    __syncthreads();
    g_hnT[((long)b * NTOK + n0 + threadIdx.y) * CCH + c0 + threadIdx.x] =
        t[threadIdx.x][threadIdx.y];
}

// ---------------- pack weights -> bf16 (+bias concat) ------------------------
__global__ void pack_k(const float* __restrict__ wq, const float* __restrict__ wk,
                       const float* __restrict__ wv, const float* __restrict__ wp,
                       const float* __restrict__ bq, const float* __restrict__ bk,
                       const float* __restrict__ bv) {
    int i = blockIdx.x * 256 + threadIdx.x;
    int sel = i >> 16, off = i & 65535;
    const float* src = sel == 0 ? wq : sel == 1 ? wk : sel == 2 ? wv : wp;
    g_wpack[i] = __float2bfloat16(src[off]);
    if (i < 768) {
        const float* bs = i < 256 ? bq : i < 512 ? bk : bv;
        g_bqkv[i] = bs[i & 255];
    }
}

// ---------------- launch -----------------------------------------------------
extern "C" void kernel_launch(void* const* d_in, const int* in_sizes, int n_in,
                              void* d_out, int out_size) {
    const float* x     = (const float*)d_in[0];
    const float* gamma = (const float*)d_in[1];
    const float* beta  = (const float*)d_in[2];
    const float* wq    = (const float*)d_in[3];
    const float* bq    = (const float*)d_in[4];
    const float* wk    = (const float*)d_in[5];
    const float* bk    = (const float*)d_in[6];
    const float* wv    = (const float*)d_in[7];
    const float* bv    = (const float*)d_in[8];
    const float* wp    = (const float*)d_in[9];
    const float* bp    = (const float*)d_in[10];
    float* out = (float*)d_out;

    __nv_bfloat16 *p_wpack, *p_hnT, *p_qkv;
    float *p_bqkv, *p_oap, *p_rsp;
    cudaGetSymbolAddress((void**)&p_wpack, g_wpack);
    cudaGetSymbolAddress((void**)&p_bqkv,  g_bqkv);
    cudaGetSymbolAddress((void**)&p_hnT,   g_hnT);
    cudaGetSymbolAddress((void**)&p_qkv,   g_qkv);
    cudaGetSymbolAddress((void**)&p_oap,   g_oap);
    cudaGetSymbolAddress((void**)&p_rsp,   g_rsp);

    const int GEMM_SMEM  = 3 * 24576;            // 72KB
    const int FLASH_SMEM = 81920 + 2 * 65536;    // 208KB
    cudaFuncSetAttribute(gemm_mma<1>, cudaFuncAttributeMaxDynamicSharedMemorySize, GEMM_SMEM);
    cudaFuncSetAttribute(gemm_mma<1>, cudaFuncAttributePreferredSharedMemoryCarveout, 100);
    cudaFuncSetAttribute(gemm_mma<2>, cudaFuncAttributeMaxDynamicSharedMemorySize, GEMM_SMEM);
    cudaFuncSetAttribute(gemm_mma<2>, cudaFuncAttributePreferredSharedMemoryCarveout, 100);
    cudaFuncSetAttribute(flash_k,  cudaFuncAttributeMaxDynamicSharedMemorySize, FLASH_SMEM);
    cudaFuncSetAttribute(flash_k,  cudaFuncAttributePreferredSharedMemoryCarveout, 100);

    gn_stats_k<<<BSZ * NGRP, 1024>>>(x);
    gn_apply_t_k<<<dim3(NTOK / 32, CCH / 32, BSZ), dim3(32, 32)>>>(x, gamma, beta);
    pack_k<<<1024, 256>>>(wq, wk, wv, wp, bq, bk, bv);

    const int M = BSZ * NTOK;   // 8192

    // qkv [m][768] = hnT [m][256] x wpack[0:768][256]^T + bqkv (q scaled 1/16)
    gemm_mma<1><<<dim3(768 / 128, M / 64), 128, GEMM_SMEM>>>(
        p_hnT, p_wpack, p_qkv, p_bqkv, nullptr);

    // fused attention (kv-split = 2)
    flash_k<<<dim3(NTOK / 128, BSZ, 2), 256, FLASH_SMEM>>>(p_qkv, p_oap, p_rsp);

    // out[b][c][n] = x + wp * combine(oap)^T + bp   (combine fused into B load)
    gemm_mma<2><<<dim3(M / 128, CCH / 64), 128, GEMM_SMEM>>>(
        p_wpack + 768 * CCH, nullptr, out, bp, x);
}

// round 12
// speedup vs baseline: 1.0743x; 1.0743x over previous
#include <cuda_runtime.h>
#include <cuda_bf16.h>
#include <math.h>
#include <stdint.h>

#define BSZ  2
#define CCH  256
#define NTOK 4096
#define NGRP 16
#define CPG  (CCH/NGRP)   // 16

// ---------------- scratch (device globals) ----------------------------------
__device__ __nv_bfloat16 g_wpack[1024*CCH];          // rows 0-767: wq|wk|wv, 768-1023: wp
__device__ float         g_bqkv[768];
__device__ __nv_bfloat16 g_hnT[BSZ*NTOK*CCH];        // [b*n][c]
__device__ __nv_bfloat16 g_qkv[BSZ*NTOK*768];        // [b*n][q|k|v], q pre-scaled 1/16
__device__ __nv_bfloat16 g_ho [BSZ*NTOK*CCH];        // [b*n][c]
__device__ float         g_oap[2][BSZ*NTOK*CCH];     // partial O per kv-split
__device__ float         g_rsp[2][BSZ*NTOK];         // partial rowsums
__device__ float         g_stats[BSZ*NGRP*2];

// ---------------- PTX helpers (sm_80-level only) -----------------------------
__device__ __forceinline__ uint32_t smem_u32(const void* p) {
    uint32_t a;
    asm("{ .reg .u64 t; cvta.to.shared.u64 t, %1; cvt.u32.u64 %0, t; }" : "=r"(a) : "l"(p));
    return a;
}
__device__ __forceinline__ void cp16(uint32_t s, const void* g) {
    asm volatile("cp.async.cg.shared.global [%0], [%1], 16;" :: "r"(s), "l"(g));
}
__device__ __forceinline__ void cp_commit() {
    asm volatile("cp.async.commit_group;" ::: "memory");
}
template<int N>
__device__ __forceinline__ void cp_wait() {
    asm volatile("cp.async.wait_group %0;" :: "n"(N) : "memory");
}
__device__ __forceinline__ void ldm4(uint32_t* r, uint32_t a) {
    asm volatile("ldmatrix.sync.aligned.m8n8.x4.shared.b16 {%0,%1,%2,%3}, [%4];"
                 : "=r"(r[0]), "=r"(r[1]), "=r"(r[2]), "=r"(r[3]) : "r"(a));
}
__device__ __forceinline__ void ldm4t(uint32_t* r, uint32_t a) {
    asm volatile("ldmatrix.sync.aligned.m8n8.x4.trans.shared.b16 {%0,%1,%2,%3}, [%4];"
                 : "=r"(r[0]), "=r"(r[1]), "=r"(r[2]), "=r"(r[3]) : "r"(a));
}
__device__ __forceinline__ void sts32(uint32_t a, uint32_t v) {
    asm volatile("st.shared.b32 [%0], %1;" :: "r"(a), "r"(v) : "memory");
}
__device__ __forceinline__ void mma_bf16(float* c, const uint32_t* a, const uint32_t* b) {
    asm volatile(
        "mma.sync.aligned.m16n8k16.row.col.f32.bf16.bf16.f32 "
        "{%0,%1,%2,%3}, {%4,%5,%6,%7}, {%8,%9}, {%0,%1,%2,%3};"
        : "+f"(c[0]), "+f"(c[1]), "+f"(c[2]), "+f"(c[3])
        : "r"(a[0]), "r"(a[1]), "r"(a[2]), "r"(a[3]), "r"(b[0]), "r"(b[1]));
}

// ---------------- small-tile QKV GEMM: 64x128 tiles, 128 threads -------------
// qkv[m][768] = hnT[m][256] x wpack[0:768][256]^T + bias (q cols scaled 1/16).
__global__ void __launch_bounds__(128, 3)
gemm_qkv(const __nv_bfloat16* __restrict__ A, const __nv_bfloat16* __restrict__ Bm,
         __nv_bfloat16* __restrict__ Cm, const float* __restrict__ bias) {
    extern __shared__ char smem[];
    const uint32_t sbase = smem_u32(smem);
    const int tid = threadIdx.x;
    const int wid = tid >> 5, lane = tid & 31;
    const int bm = blockIdx.y * 64, bn = blockIdx.x * 128;
    const int K = 256;

    const __nv_bfloat16* Ab = A + (long)bm * K;
    const __nv_bfloat16* Bb = Bm + (long)bn * K;

    const int wm = (wid >> 1) * 32;
    const int wn = (wid & 1) * 64;

    float acc[2][8][4] = {};

    auto issueA = [&](int st, int k0) {
        uint32_t sa = sbase + st * 24576;
        #pragma unroll
        for (int j = 0; j < 4; j++) {
            int idx = tid + j * 128;
            int row = idx >> 3, ch = idx & 7;
            cp16(sa + row * 128 + ((ch ^ (row & 7)) << 4),
                 Ab + (long)row * K + k0 + ch * 8);
        }
    };
    auto issueB = [&](int st, int k0) {
        uint32_t sb = sbase + st * 24576 + 8192;
        #pragma unroll
        for (int j = 0; j < 8; j++) {
            int idx = tid + j * 128;
            int row = idx >> 3, ch = idx & 7;
            cp16(sb + row * 128 + ((ch ^ (row & 7)) << 4),
                 Bb + (long)row * K + k0 + ch * 8);
        }
    };

    issueA(0, 0);  issueB(0, 0);  cp_commit();
    issueA(1, 64); issueB(1, 64); cp_commit();

    for (int it = 0; it < 4; it++) {
        cp_wait<1>();
        __syncthreads();
        const int st = it % 3;
        uint32_t a_base = sbase + st * 24576;
        uint32_t b_base = a_base + 8192;

        const int rowa = wm + (lane & 15);
        const int swa = rowa & 7;
        const int rowb = wn + ((lane >> 4) & 1) * 8 + (lane & 7);

        #pragma unroll
        for (int ks = 0; ks < 4; ks++) {
            uint32_t af[2][4];
            const int chA = ks * 2 + (lane >> 4);
            #pragma unroll
            for (int mi = 0; mi < 2; mi++)
                ldm4(af[mi], a_base + (rowa + mi * 16) * 128 + ((chA ^ swa) << 4));

            uint32_t bf[8][2];
            const int chB = ks * 2 + ((lane >> 3) & 1);
            #pragma unroll
            for (int np = 0; np < 4; np++) {
                int rb = rowb + np * 16;
                uint32_t r[4];
                ldm4(r, b_base + rb * 128 + ((chB ^ (rb & 7)) << 4));
                bf[np * 2][0] = r[0]; bf[np * 2][1] = r[1];
                bf[np * 2 + 1][0] = r[2]; bf[np * 2 + 1][1] = r[3];
            }
            #pragma unroll
            for (int mi = 0; mi < 2; mi++)
                #pragma unroll
                for (int ni = 0; ni < 8; ni++)
                    mma_bf16(acc[mi][ni], af[mi], bf[ni]);
        }
        __syncthreads();
        if (it + 2 < 4) {
            int ns = (it + 2) % 3;
            issueA(ns, (it + 2) * 64); issueB(ns, (it + 2) * 64);
        }
        cp_commit();
    }

    const int r0 = bm + wm + (lane >> 2);
    const int c0 = bn + wn + (lane & 3) * 2;
    #pragma unroll
    for (int mi = 0; mi < 2; mi++) {
        #pragma unroll
        for (int ni = 0; ni < 8; ni++) {
            int rr = r0 + mi * 16;
            int cc = c0 + ni * 8;
            float b0 = bias[cc], b1 = bias[cc + 1];
            float v0 = acc[mi][ni][0] + b0;
            float v1 = acc[mi][ni][1] + b1;
            float v2 = acc[mi][ni][2] + b0;
            float v3 = acc[mi][ni][3] + b1;
            if (cc < 256) { v0 *= 0.0625f; v1 *= 0.0625f; v2 *= 0.0625f; v3 *= 0.0625f; }
            *(__nv_bfloat162*)(Cm + (long)rr * 768 + cc) = __floats2bfloat162_rn(v0, v1);
            *(__nv_bfloat162*)(Cm + (long)(rr + 8) * 768 + cc) = __floats2bfloat162_rn(v2, v3);
        }
    }
}

// ---------------- proj GEMM (R9 proven): 128x128, 256 threads ----------------
// out[b][c][n] = x + wp[c][:] . ho[n][:] + bp[c]
__global__ void __launch_bounds__(256, 2)
gemm_proj(const __nv_bfloat16* __restrict__ A, const __nv_bfloat16* __restrict__ Bm,
          float* __restrict__ Cm, const float* __restrict__ bias,
          const float* __restrict__ xres) {
    extern __shared__ char smem[];
    const uint32_t sbase = smem_u32(smem);
    const int tid = threadIdx.x;
    const int wid = tid >> 5, lane = tid & 31;
    const int bm = blockIdx.y * 128, bn = blockIdx.x * 128;
    const int K = 256;

    const __nv_bfloat16* Ab = A  + (long)bm * K;
    const __nv_bfloat16* Bb = Bm + (long)bn * K;

    const int wm = (wid >> 2) * 64;
    const int wn = (wid & 3) * 32;

    float acc[4][4][4] = {};

    auto issue = [&](int st, int k0) {
        uint32_t sa = sbase + st * 32768;
        uint32_t sbuf = sa + 16384;
        #pragma unroll
        for (int i = 0; i < 4; i++) {
            int lin = tid + i * 256;
            int row = lin >> 3, ch = lin & 7;
            uint32_t soff = row * 128 + ((ch ^ (row & 7)) << 4);
            cp16(sa   + soff, Ab + (long)row * K + k0 + ch * 8);
            cp16(sbuf + soff, Bb + (long)row * K + k0 + ch * 8);
        }
        cp_commit();
    };

    issue(0, 0);
    issue(1, 64);

    for (int it = 0; it < 4; it++) {
        cp_wait<1>();
        __syncthreads();
        const int st = it % 3;
        uint32_t a_base = sbase + st * 32768;
        uint32_t b_base = a_base + 16384;

        const int rowa = wm + (lane & 15);
        const int swa = rowa & 7;
        const int rowb = wn + ((lane >> 4) & 1) * 8 + (lane & 7);

        #pragma unroll
        for (int ks = 0; ks < 4; ks++) {
            uint32_t af[4][4];
            const int chA = ks * 2 + (lane >> 4);
            #pragma unroll
            for (int mi = 0; mi < 4; mi++)
                ldm4(af[mi], a_base + (rowa + mi * 16) * 128 + ((chA ^ swa) << 4));

            uint32_t bf[4][2];
            const int chB = ks * 2 + ((lane >> 3) & 1);
            #pragma unroll
            for (int np = 0; np < 2; np++) {
                int rb = rowb + np * 16;
                uint32_t r[4];
                ldm4(r, b_base + rb * 128 + ((chB ^ (rb & 7)) << 4));
                bf[np * 2][0] = r[0]; bf[np * 2][1] = r[1];
                bf[np * 2 + 1][0] = r[2]; bf[np * 2 + 1][1] = r[3];
            }
            #pragma unroll
            for (int mi = 0; mi < 4; mi++)
                #pragma unroll
                for (int ni = 0; ni < 4; ni++)
                    mma_bf16(acc[mi][ni], af[mi], bf[ni]);
        }
        __syncthreads();
        if (it + 2 < 4) issue((it + 2) % 3, (it + 2) << 6);
        else cp_commit();
    }

    const int r0 = bm + wm + (lane >> 2);
    const int c0 = bn + wn + (lane & 3) * 2;
    #pragma unroll
    for (int mi = 0; mi < 4; mi++) {
        #pragma unroll
        for (int ni = 0; ni < 4; ni++) {
            int rr = r0 + mi * 16;
            int cc = c0 + ni * 8;
            float ba = bias[rr], bb = bias[rr + 8];
            int b = cc >> 12, n = cc & 4095;
            long i0 = ((long)b * CCH + rr) * NTOK + n;
            long i1 = ((long)b * CCH + rr + 8) * NTOK + n;
            float2 x0 = *(const float2*)(xres + i0);
            float2 x1 = *(const float2*)(xres + i1);
            float2 o0; o0.x = acc[mi][ni][0] + ba + x0.x; o0.y = acc[mi][ni][1] + ba + x0.y;
            float2 o1; o1.x = acc[mi][ni][2] + bb + x1.x; o1.y = acc[mi][ni][3] + bb + x1.y;
            *(float2*)(Cm + i0) = o0;
            *(float2*)(Cm + i1) = o1;
        }
    }
}

// ---------------- flash v5 (R9 proven): Br=128, 8 warps, kv-split=2 ----------
__device__ __forceinline__ uint32_t fswz(int row, int byteoff) {     // 512B rows
    return (uint32_t)(row * 512 + (byteoff & ~0x70) +
                      (((((byteoff >> 4) & 7) ^ (row & 7))) << 4));
}
__device__ __forceinline__ uint32_t pswz(int row, int byteoff) {     // 128B rows
    return (uint32_t)(row * 128 + (byteoff & 15) +
                      (((((byteoff >> 4) & 7) ^ (row & 7))) << 4));
}

__global__ void __launch_bounds__(256, 1)
flash_k(const __nv_bfloat16* __restrict__ qkv,
        float* __restrict__ oap, float* __restrict__ rsp) {
    extern __shared__ char smem[];
    const uint32_t sQ = smem_u32(smem);
    const uint32_t sP = sQ + 65536;
    const uint32_t sKV = sQ + 81920;
    const int tid = threadIdx.x, wid = tid >> 5, lane = tid & 31;
    const int m = wid >> 1, kvh = wid & 1;
    const int qt = blockIdx.x, b = blockIdx.y, sp = blockIdx.z;

    const __nv_bfloat16* qg = qkv + ((long)b * NTOK + qt * 128) * 768;
    const __nv_bfloat16* kg = qkv + ((long)b * NTOK + sp * (NTOK / 2)) * 768 + 256;
    const __nv_bfloat16* vg = kg + 256;

    #pragma unroll
    for (int j = 0; j < 16; j++) {
        int idx = tid + j * 256;
        int row = idx >> 5, ch = idx & 31;
        cp16(sQ + fswz(row, ch * 16), qg + (long)row * 768 + ch * 8);
    }
    auto loadKV = [&](int it, int stage) {
        const __nv_bfloat16* kt = kg + (long)it * 64 * 768;
        const __nv_bfloat16* vt = vg + (long)it * 64 * 768;
        uint32_t sK = sKV + stage * 65536;
        uint32_t sV = sK + 32768;
        #pragma unroll
        for (int j = 0; j < 8; j++) {
            int idx = tid + j * 256;
            int row = idx >> 5, ch = idx & 31;
            cp16(sK + fswz(row, ch * 16), kt + (long)row * 768 + ch * 8);
            cp16(sV + fswz(row, ch * 16), vt + (long)row * 768 + ch * 8);
        }
        cp_commit();
    };
    loadKV(0, 0);

    float oacc[2][16][4] = {};
    float rs[4] = {0.f, 0.f, 0.f, 0.f};
    const int NIT = NTOK / 2 / 64;   // 32

    for (int it = 0; it < NIT; it++) {
        cp_wait<0>();
        __syncthreads();
        if (it + 1 < NIT) loadKV(it + 1, (it + 1) & 1);

        uint32_t sK = sKV + (it & 1) * 65536;
        uint32_t sV = sK + 32768;

        {
            float sacc[2][4][4] = {};
            const int qrow = m * 32 + (lane & 15);
            const int qh = ((lane >> 4) & 1) * 16;
            const int krow = kvh * 32 + ((lane >> 4) & 1) * 8 + (lane & 7);
            const int kh = ((lane >> 3) & 1) * 16;
            #pragma unroll
            for (int kk = 0; kk < 16; kk++) {
                uint32_t aq[2][4];
                ldm4(aq[0], sQ + fswz(qrow,      kk * 32 + qh));
                ldm4(aq[1], sQ + fswz(qrow + 16, kk * 32 + qh));
                #pragma unroll
                for (int nb = 0; nb < 2; nb++) {
                    uint32_t r[4];
                    ldm4(r, sK + fswz(krow + nb * 16, kk * 32 + kh));
                    uint32_t b0[2] = {r[0], r[1]}, b1[2] = {r[2], r[3]};
                    #pragma unroll
                    for (int mi = 0; mi < 2; mi++) {
                        mma_bf16(sacc[mi][nb * 2],     aq[mi], b0);
                        mma_bf16(sacc[mi][nb * 2 + 1], aq[mi], b1);
                    }
                }
            }
            #pragma unroll
            for (int mi = 0; mi < 2; mi++)
                #pragma unroll
                for (int nj = 0; nj < 4; nj++) {
                    float e0 = __expf(sacc[mi][nj][0]);
                    float e1 = __expf(sacc[mi][nj][1]);
                    float e2 = __expf(sacc[mi][nj][2]);
                    float e3 = __expf(sacc[mi][nj][3]);
                    rs[mi * 2]     += e0 + e1;
                    rs[mi * 2 + 1] += e2 + e3;
                    __nv_bfloat162 p0 = __floats2bfloat162_rn(e0, e1);
                    __nv_bfloat162 p1 = __floats2bfloat162_rn(e2, e3);
                    int prow = m * 32 + mi * 16 + (lane >> 2);
                    int pcol = (kvh * 32 + nj * 8 + (lane & 3) * 2) * 2;
                    sts32(sP + pswz(prow,     pcol), *(uint32_t*)&p0);
                    sts32(sP + pswz(prow + 8, pcol), *(uint32_t*)&p1);
                }
        }
        __syncthreads();

        const int vrow0 = (lane & 7) + ((lane >> 3) & 1) * 8;
        const int vh = ((lane >> 4) & 1) * 16;
        #pragma unroll
        for (int T = 0; T < 4; T++) {
            uint32_t pa[2][4];
            #pragma unroll
            for (int mi = 0; mi < 2; mi++) {
                int arow = m * 32 + mi * 16 + (lane & 15);
                int abyte = T * 32 + ((lane >> 4) & 1) * 16;
                ldm4(pa[mi], sP + pswz(arow, abyte));
            }
            const int vr = T * 16 + vrow0;
            #pragma unroll
            for (int cb = 0; cb < 8; cb++) {
                uint32_t vb[4];
                ldm4t(vb, sV + fswz(vr, kvh * 256 + cb * 32 + vh));
                #pragma unroll
                for (int mi = 0; mi < 2; mi++) {
                    mma_bf16(oacc[mi][cb * 2],     pa[mi], vb);
                    mma_bf16(oacc[mi][cb * 2 + 1], pa[mi], vb + 2);
                }
            }
        }
    }
    __syncthreads();

    #pragma unroll
    for (int j = 0; j < 4; j++) {
        rs[j] += __shfl_xor_sync(0xFFFFFFFFu, rs[j], 1);
        rs[j] += __shfl_xor_sync(0xFFFFFFFFu, rs[j], 2);
    }
    float* rsb = (float*)(smem + 81920);
    if (kvh == 1 && (lane & 3) == 0) {
        #pragma unroll
        for (int mi = 0; mi < 2; mi++)
            #pragma unroll
            for (int h = 0; h < 2; h++)
                rsb[m * 32 + mi * 16 + h * 8 + (lane >> 2)] = rs[mi * 2 + h];
    }
    __syncthreads();
    long tokbase = (long)b * NTOK + qt * 128 + m * 32;
    if (kvh == 0 && (lane & 3) == 0) {
        #pragma unroll
        for (int mi = 0; mi < 2; mi++)
            #pragma unroll
            for (int h = 0; h < 2; h++) {
                int r = mi * 16 + h * 8 + (lane >> 2);
                rsp[(long)sp * BSZ * NTOK + tokbase + r] = rs[mi * 2 + h] + rsb[m * 32 + r];
            }
    }
    float* ob = oap + (long)sp * BSZ * NTOK * CCH;
    int r = lane >> 2, cq = (lane & 3) * 2;
    #pragma unroll
    for (int mi = 0; mi < 2; mi++) {
        long row0 = tokbase + mi * 16 + r;
        #pragma unroll
        for (int j = 0; j < 16; j++) {
            int col = kvh * 128 + j * 8 + cq;
            float2 p0; p0.x = oacc[mi][j][0]; p0.y = oacc[mi][j][1];
            float2 p1; p1.x = oacc[mi][j][2]; p1.y = oacc[mi][j][3];
            *(float2*)(ob + row0 * CCH + col) = p0;
            *(float2*)(ob + (row0 + 8) * CCH + col) = p1;
        }
    }
}

// ---------------- combine kv-split partials -> bf16 ho -----------------------
__global__ void combine_k() {
    int idx = blockIdx.x * 256 + threadIdx.x;
    long t = idx >> 6;
    int c = (idx & 63) * 4;
    float inv = 1.0f / (g_rsp[0][t] + g_rsp[1][t]);
    const float4 a = *(const float4*)&g_oap[0][t * CCH + c];
    const float4 d = *(const float4*)&g_oap[1][t * CCH + c];
    __nv_bfloat162 o0 = __floats2bfloat162_rn((a.x + d.x) * inv, (a.y + d.y) * inv);
    __nv_bfloat162 o1 = __floats2bfloat162_rn((a.z + d.z) * inv, (a.w + d.w) * inv);
    uint2 pk; pk.x = *(uint32_t*)&o0; pk.y = *(uint32_t*)&o1;
    *(uint2*)&g_ho[t * CCH + c] = pk;
}

// ---------------- GroupNorm stats (float4, 1024 threads) ---------------------
__global__ void gn_stats_k(const float* __restrict__ x) {
    int bg = blockIdx.x;
    int b = bg >> 4, g = bg & 15;
    const float4* base = (const float4*)(x + ((long)b * CCH + (long)g * CPG) * NTOK);
    float s = 0.f, s2 = 0.f;
    #pragma unroll 4
    for (int i = threadIdx.x; i < CPG * NTOK / 4; i += 1024) {
        float4 v = base[i];
        s  += v.x + v.y + v.z + v.w;
        s2 += v.x * v.x + v.y * v.y + v.z * v.z + v.w * v.w;
    }
    __shared__ float r1[1024], r2[1024];
    r1[threadIdx.x] = s; r2[threadIdx.x] = s2;
    __syncthreads();
    for (int st = 512; st > 0; st >>= 1) {
        if (threadIdx.x < st) {
            r1[threadIdx.x] += r1[threadIdx.x + st];
            r2[threadIdx.x] += r2[threadIdx.x + st];
        }
        __syncthreads();
    }
    if (threadIdx.x == 0) {
        const float invn = 1.0f / (float)(CPG * NTOK);
        float m = r1[0] * invn;
        float var = r2[0] * invn - m * m;
        g_stats[bg * 2] = m;
        g_stats[bg * 2 + 1] = rsqrtf(var + 1e-6f);
    }
}

// --------- fused GroupNorm-apply + transpose -> bf16 [b*n][c] ----------------
__global__ void gn_apply_t_k(const float* __restrict__ x,
                             const float* __restrict__ gamma,
                             const float* __restrict__ beta) {
    __shared__ __nv_bfloat16 t[32][33];
    int n0 = blockIdx.x * 32, c0 = blockIdx.y * 32, b = blockIdx.z;
    int c = c0 + threadIdx.y;
    int g = c >> 4;
    float m = g_stats[(b * NGRP + g) * 2];
    float r = g_stats[(b * NGRP + g) * 2 + 1];
    float v = x[((long)b * CCH + c) * NTOK + n0 + threadIdx.x];
    t[threadIdx.y][threadIdx.x] = __float2bfloat16((v - m) * r * gamma[c] + beta[c]);
    __syncthreads();
    g_hnT[((long)b * NTOK + n0 + threadIdx.y) * CCH + c0 + threadIdx.x] =
        t[threadIdx.x][threadIdx.y];
}

// ---------------- pack weights -> bf16 (+bias concat) ------------------------
__global__ void pack_k(const float* __restrict__ wq, const float* __restrict__ wk,
                       const float* __restrict__ wv, const float* __restrict__ wp,
                       const float* __restrict__ bq, const float* __restrict__ bk,
                       const float* __restrict__ bv) {
    int i = blockIdx.x * 256 + threadIdx.x;
    int sel = i >> 16, off = i & 65535;
    const float* src = sel == 0 ? wq : sel == 1 ? wk : sel == 2 ? wv : wp;
    g_wpack[i] = __float2bfloat16(src[off]);
    if (i < 768) {
        const float* bs = i < 256 ? bq : i < 512 ? bk : bv;
        g_bqkv[i] = bs[i & 255];
    }
}

// ---------------- launch -----------------------------------------------------
extern "C" void kernel_launch(void* const* d_in, const int* in_sizes, int n_in,
                              void* d_out, int out_size) {
    const float* x     = (const float*)d_in[0];
    const float* gamma = (const float*)d_in[1];
    const float* beta  = (const float*)d_in[2];
    const float* wq    = (const float*)d_in[3];
    const float* bq    = (const float*)d_in[4];
    const float* wk    = (const float*)d_in[5];
    const float* bk    = (const float*)d_in[6];
    const float* wv    = (const float*)d_in[7];
    const float* bv    = (const float*)d_in[8];
    const float* wp    = (const float*)d_in[9];
    const float* bp    = (const float*)d_in[10];
    float* out = (float*)d_out;

    __nv_bfloat16 *p_wpack, *p_hnT, *p_qkv, *p_ho;
    float *p_bqkv, *p_oap, *p_rsp;
    cudaGetSymbolAddress((void**)&p_wpack, g_wpack);
    cudaGetSymbolAddress((void**)&p_bqkv,  g_bqkv);
    cudaGetSymbolAddress((void**)&p_hnT,   g_hnT);
    cudaGetSymbolAddress((void**)&p_qkv,   g_qkv);
    cudaGetSymbolAddress((void**)&p_ho,    g_ho);
    cudaGetSymbolAddress((void**)&p_oap,   g_oap);
    cudaGetSymbolAddress((void**)&p_rsp,   g_rsp);

    const int QKV_SMEM   = 3 * 24576;            // 72KB
    const int PROJ_SMEM  = 3 * 32768;            // 96KB
    const int FLASH_SMEM = 81920 + 2 * 65536;    // 208KB
    cudaFuncSetAttribute(gemm_qkv, cudaFuncAttributeMaxDynamicSharedMemorySize, QKV_SMEM);
    cudaFuncSetAttribute(gemm_qkv, cudaFuncAttributePreferredSharedMemoryCarveout, 100);
    cudaFuncSetAttribute(gemm_proj, cudaFuncAttributeMaxDynamicSharedMemorySize, PROJ_SMEM);
    cudaFuncSetAttribute(gemm_proj, cudaFuncAttributePreferredSharedMemoryCarveout, 100);
    cudaFuncSetAttribute(flash_k, cudaFuncAttributeMaxDynamicSharedMemorySize, FLASH_SMEM);
    cudaFuncSetAttribute(flash_k, cudaFuncAttributePreferredSharedMemoryCarveout, 100);

    gn_stats_k<<<BSZ * NGRP, 1024>>>(x);
    gn_apply_t_k<<<dim3(NTOK / 32, CCH / 32, BSZ), dim3(32, 32)>>>(x, gamma, beta);
    pack_k<<<1024, 256>>>(wq, wk, wv, wp, bq, bk, bv);

    const int M = BSZ * NTOK;   // 8192

    // qkv [m][768] = hnT [m][256] x wpack[0:768][256]^T + bqkv (q scaled 1/16)
    gemm_qkv<<<dim3(768 / 128, M / 64), 128, QKV_SMEM>>>(p_hnT, p_wpack, p_qkv, p_bqkv);

    // fused attention (kv-split = 2)
    flash_k<<<dim3(NTOK / 128, BSZ, 2), 256, FLASH_SMEM>>>(p_qkv, p_oap, p_rsp);
    combine_k<<<M * 64 / 256, 256>>>();

    // out[b][c][n] = x + wp ho^T + bp
    gemm_proj<<<dim3(M / 128, CCH / 128), 256, PROJ_SMEM>>>(
        p_wpack + 768 * CCH, p_ho, out, bp, x);
}